// round 7
// baseline (speedup 1.0000x reference)
#include <cuda_runtime.h>
#include <cstdint>

// Retrace_9844065042706 — affine-segment scan, cp.async smem staging.
// Pass1: block = 4 b x 16 d over a 16-step segment (64 thr, 22KB smem ->
// ~10 blocks/SM for copy/compute phase diversity). Per-segment loss is
// quadratic in incoming carry: alpha - 2 beta c + delta c^2; carry map (A,M).
// Pass2: one warp per chain, 32 lanes = 32 segments, shuffle-tree compose.

#define RB 2048
#define RT 512
#define RD 16
#define SEG 32
#define SEGLEN 16
#define NJ (RT - 1)            // 511
#define BD (RB * RD)           // 32768 chains
#define NBL 4                  // b's per block
#define NTH 64                 // threads (4 b x 16 d)

// smem: 5 tensors [4][16][16] (+16 pad per b), then bp [4][17]
#define BSTR  272              // 16*16 + 16
#define TS    (NBL * BSTR)     // 1088
#define BPOFF (5 * TS)         // 5440
#define BPSTR 17
#define SMEM_FLOATS (BPOFF + NBL * BPSTR)   // 5508 floats = 22032 B

static constexpr float GAMMA = 0.99f;

// Scratch, chain-major: rec[chain*SEG + s] = {A, M, beta, delta}; al separate.
__device__ float4 g_rec[(size_t)BD * SEG];
__device__ float  g_al [(size_t)BD * SEG];

__device__ __forceinline__ void cp16(uint32_t s, const void* g) {
    asm volatile("cp.async.cg.shared.global [%0], [%1], 16;" :: "r"(s), "l"(g));
}
__device__ __forceinline__ void cp4(uint32_t s, const void* g) {
    asm volatile("cp.async.ca.shared.global [%0], [%1], 4;" :: "r"(s), "l"(g));
}
__device__ __forceinline__ void cp_commit() { asm volatile("cp.async.commit_group;"); }
template <int N>
__device__ __forceinline__ void cp_wait() {
    asm volatile("cp.async.wait_group %0;" :: "n"(N));
}
__device__ __forceinline__ uint32_t smem_u32(const void* p) {
    return (uint32_t)__cvta_generic_to_shared(p);
}

__global__ void __launch_bounds__(NTH)
retrace_pass1(const float* __restrict__ Q,
              const float* __restrict__ E,
              const float* __restrict__ TQ,
              const float* __restrict__ TPP,
              const float* __restrict__ R,
              const float* __restrict__ BPP,
              float* __restrict__ out)
{
    __shared__ float sm[SMEM_FLOATS];
    const int tid = threadIdx.x;
    const int s   = blockIdx.x & (SEG - 1);
    const int bg  = blockIdx.x >> 5;           // b-group (0..511)

    if (blockIdx.x == 0 && tid == 0) out[0] = 0.0f;

    const int lo    = s * SEGLEN;
    const int steps = min(SEGLEN, NJ - lo);    // 16, or 15 for seg 31

    // ---- stage the whole tile: 5 tensors * 4b * 16k * 4 chunks = 1280 cp16
    {
        const uint32_t sbase = smem_u32(sm);
        #pragma unroll 5
        for (int i = tid; i < 1280; i += NTH) {
            const int tensor = i >> 8;
            const int rem    = i & 255;
            const int b      = rem >> 6;
            const int r2     = rem & 63;
            const int k      = r2 >> 2;
            const int d4     = r2 & 3;

            const float* gp = (tensor == 0) ? E : (tensor == 1) ? TQ
                            : (tensor == 2) ? TPP : (tensor == 3) ? R : Q;
            const int t = (tensor < 3) ? min(lo + 1 + k, RT - 1) : (lo + k);

            const size_t goff = ((size_t)(bg * NBL + b) * RT + t) * RD + d4 * 4;
            const uint32_t soff = sbase
                + (uint32_t)(tensor * TS + b * BSTR + k * RD + d4 * 4) * 4u;
            cp16(soff, gp + goff);
        }
        // bp: 4 b * 16 k = 64 entries, one per thread
        {
            const int b = tid >> 4;
            const int k = tid & 15;
            const int t = min(lo + 1 + k, RT - 1);
            cp4(sbase + (uint32_t)(BPOFF + b * BPSTR + k) * 4u,
                BPP + (size_t)(bg * NBL + b) * RT + t);
        }
        cp_commit();
    }

    const int b_l = tid >> 4;
    const int d   = tid & 15;
    const int rb  = b_l * BSTR + d;
    const int bpb = BPOFF + b_l * BPSTR;

    float q0 = 0.f, P = 1.f, al = 0.f, be = 0.f, de = 0.f;

    cp_wait<0>();
    __syncthreads();

    #pragma unroll 4
    for (int k = steps - 1; k >= 0; --k) {
        const int ro = rb + k * RD;
        const float e   = sm[ro];
        const float tq  = sm[TS + ro];
        const float tpp = sm[2 * TS + ro];
        const float r   = sm[3 * TS + ro];
        const float qv  = sm[4 * TS + ro];
        const float bp  = sm[bpb + k];

        const float c = __expf(fminf(tpp - bp, 0.f));
        const float m = GAMMA * c;
        const float a = fmaf(GAMMA, fmaf(-c, tq, e), r);
        q0 = fmaf(m, q0, a);  P *= m;
        const float u = qv - q0;
        al = fmaf(u, u, al);  be = fmaf(u, P, be);  de = fmaf(P, P, de);
    }

    const int chain = (bg * NBL + b_l) * RD + d;
    const size_t idx = (size_t)chain * SEG + s;
    g_rec[idx] = make_float4(q0, P, be, de);
    g_al[idx]  = al;
}

// ---------------------------------------------------------------------------
// Pass 2: one warp per chain; lane = segment. Records composed by 5-step
// shuffle tree. X = lower s (lower j), Y = higher s; carry flows Y -> X:
//   al'' = alY + alX - 2 beX AY + deX AY^2
//   be'' = beY + (beX - deX AY) MY
//   de'' = deY + deX MY^2
//   A''  = AX + MX AY ;  M'' = MX MY
// ---------------------------------------------------------------------------
__global__ void __launch_bounds__(128)
retrace_pass2(const float* __restrict__ TQ, float* __restrict__ out)
{
    const int gid   = blockIdx.x * blockDim.x + threadIdx.x; // 0..BD*SEG-1
    const int chain = gid >> 5;
    const int lane  = threadIdx.x & 31;   // = segment s

    const size_t idx = (size_t)chain * SEG + lane;   // warp-contiguous
    const float4 v = g_rec[idx];
    float A = v.x, M = v.y, be = v.z, de = v.w;
    float al = g_al[idx];

    #pragma unroll
    for (int k = 1; k < 32; k <<= 1) {
        const float oA  = __shfl_down_sync(0xffffffffu, A,  k);
        const float oM  = __shfl_down_sync(0xffffffffu, M,  k);
        const float oal = __shfl_down_sync(0xffffffffu, al, k);
        const float obe = __shfl_down_sync(0xffffffffu, be, k);
        const float ode = __shfl_down_sync(0xffffffffu, de, k);

        const float nal = oal + al - 2.0f * be * oA + de * oA * oA;
        const float nbe = obe + (be - de * oA) * oM;
        const float nde = ode + de * oM * oM;
        const float nA  = fmaf(M, oA, A);
        const float nM  = M * oM;
        al = nal; be = nbe; de = nde; A = nA; M = nM;
    }

    float sum = 0.0f;
    if (lane == 0) {
        const int b = chain >> 4;
        const int d = chain & 15;
        const float carry = TQ[((size_t)b * RT + (RT - 1)) * RD + d];
        sum = fmaf(carry, fmaf(de, carry, -2.0f * be), al);
    }

    __shared__ float ws[4];
    const int w = threadIdx.x >> 5;
    if (lane == 0) ws[w] = sum;
    __syncthreads();

    if (w == 0) {
        float x = (lane < 4) ? ws[lane] : 0.0f;
        #pragma unroll
        for (int o = 2; o > 0; o >>= 1)
            x += __shfl_down_sync(0xffffffffu, x, o);
        if (lane == 0) {
            const float invN = 1.0f / ((float)RB * (float)NJ * (float)RD);
            atomicAdd(out, x * invN);
        }
    }
}

extern "C" void kernel_launch(void* const* d_in, const int* in_sizes, int n_in,
                              void* d_out, int out_size)
{
    const float* Q   = (const float*)d_in[0];
    const float* E   = (const float*)d_in[1];
    const float* TQ  = (const float*)d_in[2];
    const float* R   = (const float*)d_in[3];
    const float* TPP = (const float*)d_in[4];
    const float* BPP = (const float*)d_in[5];
    float* out = (float*)d_out;

    // Pass 1: 512 b-groups x 32 segments = 16384 blocks of 64 threads
    retrace_pass1<<<(RB / NBL) * SEG, NTH>>>(Q, E, TQ, TPP, R, BPP, out);

    // Pass 2: BD warps = 1048576 threads / 128
    retrace_pass2<<<(BD * 32) / 128, 128>>>(TQ, out);
}

// round 8
// speedup vs baseline: 1.1476x; 1.1476x over previous
#include <cuda_runtime.h>
#include <cstdint>

// Retrace_9844065042706 — affine-segment scan, cp.async smem staging.
// Pass1 (R6 config): block = 4 b x 16 d over a 32-step segment, 64 threads,
// 42.8KB smem -> 5 resident blocks/SM for copy/compute phase diversity.
// Records stored dense, seg-major: g4[s][chain]={A,M,beta,delta}, gal[s][chain].
// Pass2: thread-per-chain serial compose over 16 segments (coalesced 16B loads).

#define RB 2048
#define RT 512
#define RD 16
#define SEG 16
#define SEGLEN 32
#define NJ (RT - 1)            // 511
#define BD (RB * RD)           // 32768 chains
#define NBL 4                  // b's per block
#define NTH 64                 // threads (4 b x 16 d)

// smem layout (floats): 5 tensors [4][32][16] (+16 pad per b), then bp [4][33]
#define BSTR  528
#define TS    (NBL * BSTR)     // 2112
#define BPOFF (5 * TS)         // 10560
#define BPSTR 33
#define SMEM_FLOATS (BPOFF + NBL * BPSTR)   // 10692 -> 42768 B
#define SMEM_BYTES  (SMEM_FLOATS * 4)

static constexpr float GAMMA = 0.99f;

// Dense scratch, seg-major (coalesced across chain in both passes): 10 MB
__device__ float4 g4 [(size_t)SEG * BD];   // {A, M, beta, delta}
__device__ float  gal[(size_t)SEG * BD];   // alpha

__device__ __forceinline__ void cp16(uint32_t s, const void* g) {
    asm volatile("cp.async.cg.shared.global [%0], [%1], 16;" :: "r"(s), "l"(g));
}
__device__ __forceinline__ void cp4(uint32_t s, const void* g) {
    asm volatile("cp.async.ca.shared.global [%0], [%1], 4;" :: "r"(s), "l"(g));
}
__device__ __forceinline__ void cp_commit() { asm volatile("cp.async.commit_group;"); }
template <int N>
__device__ __forceinline__ void cp_wait() {
    asm volatile("cp.async.wait_group %0;" :: "n"(N));
}
__device__ __forceinline__ uint32_t smem_u32(const void* p) {
    return (uint32_t)__cvta_generic_to_shared(p);
}

// copy rows [k0, k0+16) of the tile (5 tensors + bp)
__device__ __forceinline__ void copy_half(
    float* sm, int tid, int bg, int lo, int k0,
    const float* __restrict__ E, const float* __restrict__ TQ,
    const float* __restrict__ TPP, const float* __restrict__ R,
    const float* __restrict__ Q, const float* __restrict__ BPP)
{
    const uint32_t sbase = smem_u32(sm);
    #pragma unroll 5
    for (int i = tid; i < 1280; i += NTH) {
        const int tensor = i >> 8;
        const int rem    = i & 255;
        const int b      = rem >> 6;
        const int r2     = rem & 63;
        const int k      = k0 + (r2 >> 2);
        const int d4     = r2 & 3;

        const float* gp = (tensor == 0) ? E : (tensor == 1) ? TQ
                        : (tensor == 2) ? TPP : (tensor == 3) ? R : Q;
        const int t = (tensor < 3) ? min(lo + 1 + k, RT - 1) : (lo + k);

        const size_t goff = ((size_t)(bg * NBL + b) * RT + t) * RD + d4 * 4;
        const uint32_t soff = sbase
            + (uint32_t)(tensor * TS + b * BSTR + k * RD + d4 * 4) * 4u;
        cp16(soff, gp + goff);
    }
    {
        const int b = tid >> 4;
        const int k = k0 + (tid & 15);
        const int t = min(lo + 1 + k, RT - 1);
        cp4(sbase + (uint32_t)(BPOFF + b * BPSTR + k) * 4u,
            BPP + (size_t)(bg * NBL + b) * RT + t);
    }
    cp_commit();
}

__global__ void __launch_bounds__(NTH)
retrace_pass1(const float* __restrict__ Q,
              const float* __restrict__ E,
              const float* __restrict__ TQ,
              const float* __restrict__ TPP,
              const float* __restrict__ R,
              const float* __restrict__ BPP,
              float* __restrict__ out)
{
    extern __shared__ float sm[];
    const int tid = threadIdx.x;
    const int s   = blockIdx.x & (SEG - 1);
    const int bg  = blockIdx.x >> 4;           // 0..511

    if (blockIdx.x == 0 && tid == 0) out[0] = 0.0f;

    const int lo    = s * SEGLEN;
    const int steps = min(SEGLEN, NJ - lo);    // 32, or 31 for seg 15

    // high half first (scanned first), then low half
    copy_half(sm, tid, bg, lo, 16, E, TQ, TPP, R, Q, BPP);
    copy_half(sm, tid, bg, lo, 0,  E, TQ, TPP, R, Q, BPP);

    const int b_l = tid >> 4;
    const int d   = tid & 15;
    const int rb  = b_l * BSTR + d;
    const int bpb = BPOFF + b_l * BPSTR;

    float q0 = 0.f, P = 1.f, al = 0.f, be = 0.f, de = 0.f;

    cp_wait<1>();
    __syncthreads();

    #pragma unroll 4
    for (int k = steps - 1; k >= 16; --k) {
        const int ro = rb + k * RD;
        const float e   = sm[ro];
        const float tq  = sm[TS + ro];
        const float tpp = sm[2 * TS + ro];
        const float r   = sm[3 * TS + ro];
        const float qv  = sm[4 * TS + ro];
        const float bp  = sm[bpb + k];

        const float c = __expf(fminf(tpp - bp, 0.f));
        const float m = GAMMA * c;
        const float a = fmaf(GAMMA, fmaf(-c, tq, e), r);
        q0 = fmaf(m, q0, a);  P *= m;
        const float u = qv - q0;
        al = fmaf(u, u, al);  be = fmaf(u, P, be);  de = fmaf(P, P, de);
    }

    cp_wait<0>();
    __syncthreads();

    #pragma unroll 4
    for (int k = 15; k >= 0; --k) {
        const int ro = rb + k * RD;
        const float e   = sm[ro];
        const float tq  = sm[TS + ro];
        const float tpp = sm[2 * TS + ro];
        const float r   = sm[3 * TS + ro];
        const float qv  = sm[4 * TS + ro];
        const float bp  = sm[bpb + k];

        const float c = __expf(fminf(tpp - bp, 0.f));
        const float m = GAMMA * c;
        const float a = fmaf(GAMMA, fmaf(-c, tq, e), r);
        q0 = fmaf(m, q0, a);  P *= m;
        const float u = qv - q0;
        al = fmaf(u, u, al);  be = fmaf(u, P, be);  de = fmaf(P, P, de);
    }

    const int chain = (bg * NBL + b_l) * RD + d;
    const size_t idx = (size_t)s * BD + chain;   // seg-major, chain-contiguous
    g4 [idx] = make_float4(q0, P, be, de);
    gal[idx] = al;
}

// ---------------------------------------------------------------------------
// Pass 2: thread per chain, serial compose over 16 segments (high s -> low s).
// Loads coalesced: warp = 32 consecutive chains at each s (512B contiguous).
// ---------------------------------------------------------------------------
__global__ void __launch_bounds__(128)
retrace_pass2(const float* __restrict__ TQ, float* __restrict__ out)
{
    const int bd = blockIdx.x * blockDim.x + threadIdx.x;
    const int d  = bd & (RD - 1);
    const int b  = bd >> 4;

    float carry = TQ[((size_t)b * RT + (RT - 1)) * RD + d];
    float sum = 0.0f;

    #pragma unroll
    for (int s = SEG - 1; s >= 0; --s) {
        const size_t idx = (size_t)s * BD + bd;
        const float4 v = g4[idx];          // A, M, be, de
        const float  al = gal[idx];
        sum += fmaf(carry, fmaf(v.w, carry, -2.0f * v.z), al);
        carry = fmaf(v.y, carry, v.x);
    }

    #pragma unroll
    for (int o = 16; o > 0; o >>= 1)
        sum += __shfl_down_sync(0xffffffffu, sum, o);

    __shared__ float ws[4];
    const int lane = threadIdx.x & 31;
    const int w    = threadIdx.x >> 5;
    if (lane == 0) ws[w] = sum;
    __syncthreads();

    if (w == 0) {
        float x = (lane < 4) ? ws[lane] : 0.0f;
        #pragma unroll
        for (int o = 2; o > 0; o >>= 1)
            x += __shfl_down_sync(0xffffffffu, x, o);
        if (lane == 0) {
            const float invN = 1.0f / ((float)RB * (float)NJ * (float)RD);
            atomicAdd(out, x * invN);
        }
    }
}

extern "C" void kernel_launch(void* const* d_in, const int* in_sizes, int n_in,
                              void* d_out, int out_size)
{
    const float* Q   = (const float*)d_in[0];
    const float* E   = (const float*)d_in[1];
    const float* TQ  = (const float*)d_in[2];
    const float* R   = (const float*)d_in[3];
    const float* TPP = (const float*)d_in[4];
    const float* BPP = (const float*)d_in[5];
    float* out = (float*)d_out;

    // Pass 1: 512 b-groups x 16 segments = 8192 blocks of 64 threads
    retrace_pass1<<<(RB / NBL) * SEG, NTH, SMEM_BYTES>>>(Q, E, TQ, TPP, R, BPP, out);

    // Pass 2: BD = 32768 threads
    retrace_pass2<<<BD / 128, 128>>>(TQ, out);
}